// round 1
// baseline (speedup 1.0000x reference)
#include <cuda_runtime.h>
#include <cstdint>

#define IN_F   256
#define HID    512
#define OUT_F  2048
#define NHEADS 8
#define BATCH  4096

#define TM 128
#define TN 64
#define TK 16

// ---------------- device scratch (no allocation allowed) ----------------
__device__ int   g_cnt[NHEADS];
__device__ int   g_off[NHEADS + 1];
__device__ int   g_cur[NHEADS];
__device__ int   g_perm[BATCH];
__device__ float g_h[(size_t)BATCH * HID];   // hidden activations, grouped row order

// ---------------- tiny grouping kernels ----------------
__global__ void k_init_counts() {
    int t = threadIdx.x;
    if (t < NHEADS) g_cnt[t] = 0;
}

__global__ void k_count(const int* __restrict__ idx) {
    int i = blockIdx.x * blockDim.x + threadIdx.x;
    if (i < BATCH) atomicAdd(&g_cnt[idx[i]], 1);
}

__global__ void k_prefix() {
    int s = 0;
    for (int h = 0; h < NHEADS; h++) {
        g_off[h] = s;
        g_cur[h] = s;
        s += g_cnt[h];
    }
    g_off[NHEADS] = s;
}

__global__ void k_scatter(const int* __restrict__ idx) {
    int i = blockIdx.x * blockDim.x + threadIdx.x;
    if (i < BATCH) {
        int p = atomicAdd(&g_cur[idx[i]], 1);
        g_perm[p] = i;
    }
}

// ---------------- packed f32x2 helpers ----------------
__device__ __forceinline__ unsigned long long pack2(float x, float y) {
    unsigned long long r;
    asm("mov.b64 %0, {%1, %2};" : "=l"(r) : "f"(x), "f"(y));
    return r;
}
__device__ __forceinline__ void fma2(unsigned long long& acc,
                                     unsigned long long a,
                                     unsigned long long b) {
    asm("fma.rn.f32x2 %0, %1, %2, %0;" : "+l"(acc) : "l"(a), "l"(b));
}
__device__ __forceinline__ float2 unpack2(unsigned long long v) {
    float2 f;
    asm("mov.b64 {%0, %1}, %2;" : "=f"(f.x), "=f"(f.y) : "l"(v));
    return f;
}

// ---------------- grouped GEMM ----------------
// L1 == true : A = Aext (X), rows gathered via g_perm; C = g_h (grouped rows); bias + ReLU
// L1 == false: A = g_h (grouped rows, contiguous); C = Cext (out), rows scattered via g_perm; bias only
template <bool L1>
__global__ __launch_bounds__(256, 2)
void gemm_grouped(const float* __restrict__ Aext,
                  const float* __restrict__ W,      // [NHEADS, K, N]
                  const float* __restrict__ bias,   // [NHEADS, N]
                  float* __restrict__ Cext,
                  int K, int N)
{
    const int h      = blockIdx.z;
    const int mstart = g_off[h];
    const int Mh     = g_off[h + 1] - mstart;
    const int m0     = blockIdx.y * TM;
    if (m0 >= Mh) return;
    const int n0     = blockIdx.x * TN;

    const float* A = L1 ? Aext : g_h;     // A stride = K
    float*       C = L1 ? g_h  : Cext;    // C stride = N
    const float* Wh = W + (size_t)h * K * N;

    __shared__ float As[TK][TM + 4];
    __shared__ float Bs[TK][TN + 4];

    const int tid = threadIdx.x;
    const int tx  = tid & 15;   // 0..15 -> 4 output cols
    const int ty  = tid >> 4;   // 0..15 -> 8 output rows

    unsigned long long acc[8][2];
#pragma unroll
    for (int i = 0; i < 8; i++) { acc[i][0] = 0ull; acc[i][1] = 0ull; }

    for (int k0 = 0; k0 < K; k0 += TK) {
        // ---- load A tile: TM x TK (float4 along K) ----
#pragma unroll
        for (int it = 0; it < 2; it++) {
            int e  = tid + it * 256;     // float4 index, 0..511
            int m  = e >> 2;             // 0..127
            int kv = (e & 3) * 4;        // 0,4,8,12
            float4 v = make_float4(0.f, 0.f, 0.f, 0.f);
            if (m < Mh - m0) {
                int row;
                if (L1) row = g_perm[mstart + m0 + m];
                else    row = mstart + m0 + m;
                v = *reinterpret_cast<const float4*>(&A[(size_t)row * K + k0 + kv]);
            }
            As[kv + 0][m] = v.x;
            As[kv + 1][m] = v.y;
            As[kv + 2][m] = v.z;
            As[kv + 3][m] = v.w;
        }
        // ---- load W tile: TK x TN (float4 along N) ----
        {
            int k  = tid >> 4;          // 0..15
            int nq = (tid & 15) * 4;    // 0..60
            float4 v = *reinterpret_cast<const float4*>(&Wh[(size_t)(k0 + k) * N + n0 + nq]);
            *reinterpret_cast<float4*>(&Bs[k][nq]) = v;
        }
        __syncthreads();

#pragma unroll
        for (int k = 0; k < TK; k++) {
            float4 a0 = *reinterpret_cast<const float4*>(&As[k][ty * 8]);
            float4 a1 = *reinterpret_cast<const float4*>(&As[k][ty * 8 + 4]);
            float4 w  = *reinterpret_cast<const float4*>(&Bs[k][tx * 4]);
            unsigned long long w01 = pack2(w.x, w.y);
            unsigned long long w23 = pack2(w.z, w.w);
            float av[8] = {a0.x, a0.y, a0.z, a0.w, a1.x, a1.y, a1.z, a1.w};
#pragma unroll
            for (int i = 0; i < 8; i++) {
                unsigned long long aa = pack2(av[i], av[i]);
                fma2(acc[i][0], aa, w01);
                fma2(acc[i][1], aa, w23);
            }
        }
        __syncthreads();
    }

    // ---- epilogue: bias (+ReLU for L1), write ----
    float4 bb = *reinterpret_cast<const float4*>(&bias[(size_t)h * N + n0 + tx * 4]);
#pragma unroll
    for (int i = 0; i < 8; i++) {
        int ml = m0 + ty * 8 + i;
        if (ml >= Mh) continue;
        float2 v0 = unpack2(acc[i][0]);
        float2 v1 = unpack2(acc[i][1]);
        float4 r;
        r.x = v0.x + bb.x;
        r.y = v0.y + bb.y;
        r.z = v1.x + bb.z;
        r.w = v1.y + bb.w;
        if (L1) {
            r.x = fmaxf(r.x, 0.f);
            r.y = fmaxf(r.y, 0.f);
            r.z = fmaxf(r.z, 0.f);
            r.w = fmaxf(r.w, 0.f);
        }
        int crow;
        if (L1) crow = mstart + ml;            // grouped order into g_h
        else    crow = g_perm[mstart + ml];    // scatter back to original rows
        *reinterpret_cast<float4*>(&C[(size_t)crow * N + n0 + tx * 4]) = r;
    }
}

// ---------------- launch ----------------
extern "C" void kernel_launch(void* const* d_in, const int* in_sizes, int n_in,
                              void* d_out, int out_size)
{
    const float* X   = (const float*)d_in[0];  // [4096, 256]
    const int*   idx = (const int*)  d_in[1];  // [4096]
    const float* W1  = (const float*)d_in[2];  // [8, 256, 512]
    const float* b1  = (const float*)d_in[3];  // [8, 512]
    const float* W2  = (const float*)d_in[4];  // [8, 512, 2048]
    const float* b2  = (const float*)d_in[5];  // [8, 2048]
    float*       out = (float*)d_out;          // [4096, 2048]

    k_init_counts<<<1, 32>>>();
    k_count<<<(BATCH + 255) / 256, 256>>>(idx);
    k_prefix<<<1, 1>>>();
    k_scatter<<<(BATCH + 255) / 256, 256>>>(idx);

    const int row_tiles = (BATCH + TM - 1) / TM;   // worst case: all rows in one head

    dim3 g1(HID / TN, row_tiles, NHEADS);
    gemm_grouped<true><<<g1, 256>>>(X, W1, b1, nullptr, IN_F, HID);

    dim3 g2(OUT_F / TN, row_tiles, NHEADS);
    gemm_grouped<false><<<g2, 256>>>(nullptr, W2, b2, out, HID, OUT_F);
}

// round 3
// speedup vs baseline: 1.8937x; 1.8937x over previous
#include <cuda_runtime.h>
#include <cuda_bf16.h>
#include <cstdint>

#define IN_F   256
#define HID    512
#define OUT_F  2048
#define NHEADS 8
#define BATCH  4096

// ---------------- device scratch (no allocation allowed) ----------------
__device__ int g_off[NHEADS + 1];
__device__ int g_perm[BATCH];

__device__ __align__(16) __nv_bfloat16 g_xh[BATCH * IN_F];
__device__ __align__(16) __nv_bfloat16 g_xl[BATCH * IN_F];
__device__ __align__(16) __nv_bfloat16 g_hh[BATCH * HID];   // grouped rows
__device__ __align__(16) __nv_bfloat16 g_hl[BATCH * HID];
__device__ __align__(16) __nv_bfloat16 g_w1h[NHEADS * IN_F * HID];
__device__ __align__(16) __nv_bfloat16 g_w1l[NHEADS * IN_F * HID];
__device__ __align__(16) __nv_bfloat16 g_w2h[NHEADS * HID * OUT_F];
__device__ __align__(16) __nv_bfloat16 g_w2l[NHEADS * HID * OUT_F];

// ---------------- grouping ----------------
__global__ void k_group(const int* __restrict__ idx) {
    __shared__ int cnt[NHEADS];
    __shared__ int cur[NHEADS];
    int t = threadIdx.x;                  // 1024 threads
    if (t < NHEADS) cnt[t] = 0;
    __syncthreads();
    int my[4];
#pragma unroll
    for (int i = 0; i < 4; i++) {
        my[i] = idx[t + i * 1024];
        atomicAdd(&cnt[my[i]], 1);
    }
    __syncthreads();
    if (t == 0) {
        int s = 0;
        for (int h = 0; h < NHEADS; h++) { g_off[h] = s; cur[h] = s; s += cnt[h]; }
        g_off[NHEADS] = s;
    }
    __syncthreads();
#pragma unroll
    for (int i = 0; i < 4; i++) {
        int p = atomicAdd(&cur[my[i]], 1);
        g_perm[p] = t + i * 1024;
    }
}

// ---------------- bf16 hi/lo split ----------------
__device__ __forceinline__ uint32_t pack_bf2(float a, float b) {
    uint16_t ha = __bfloat16_as_ushort(__float2bfloat16_rn(a));
    uint16_t hb = __bfloat16_as_ushort(__float2bfloat16_rn(b));
    return (uint32_t)ha | ((uint32_t)hb << 16);
}

__global__ void k_split(const float* __restrict__ src,
                        __nv_bfloat16* __restrict__ hi,
                        __nv_bfloat16* __restrict__ lo, int n4) {
    int i = blockIdx.x * blockDim.x + threadIdx.x;
    if (i >= n4) return;
    float4 v = reinterpret_cast<const float4*>(src)[i];
    float h0 = __bfloat162float(__float2bfloat16_rn(v.x));
    float h1 = __bfloat162float(__float2bfloat16_rn(v.y));
    float h2 = __bfloat162float(__float2bfloat16_rn(v.z));
    float h3 = __bfloat162float(__float2bfloat16_rn(v.w));
    uint2 uh, ul;
    uh.x = pack_bf2(h0, h1);
    uh.y = pack_bf2(h2, h3);
    ul.x = pack_bf2(v.x - h0, v.y - h1);
    ul.y = pack_bf2(v.z - h2, v.w - h3);
    reinterpret_cast<uint2*>(hi)[i] = uh;
    reinterpret_cast<uint2*>(lo)[i] = ul;
}

// ---------------- PTX helpers ----------------
__device__ __forceinline__ uint32_t smem_u32(const void* p) {
    uint32_t a;
    asm("{ .reg .u64 t; cvta.to.shared.u64 t, %1; cvt.u32.u64 %0, t; }" : "=r"(a) : "l"(p));
    return a;
}
__device__ __forceinline__ void ldsm4(uint32_t* r, uint32_t addr) {
    asm volatile("ldmatrix.sync.aligned.m8n8.x4.shared.b16 {%0,%1,%2,%3}, [%4];"
                 : "=r"(r[0]), "=r"(r[1]), "=r"(r[2]), "=r"(r[3]) : "r"(addr));
}
__device__ __forceinline__ void ldsm4t(uint32_t* r, uint32_t addr) {
    asm volatile("ldmatrix.sync.aligned.m8n8.x4.trans.shared.b16 {%0,%1,%2,%3}, [%4];"
                 : "=r"(r[0]), "=r"(r[1]), "=r"(r[2]), "=r"(r[3]) : "r"(addr));
}
__device__ __forceinline__ void mma16816(float* d, const uint32_t* a, const uint32_t* b) {
    asm volatile("mma.sync.aligned.m16n8k16.row.col.f32.bf16.bf16.f32 "
                 "{%0,%1,%2,%3}, {%4,%5,%6,%7}, {%8,%9}, {%0,%1,%2,%3};"
                 : "+f"(d[0]), "+f"(d[1]), "+f"(d[2]), "+f"(d[3])
                 : "r"(a[0]), "r"(a[1]), "r"(a[2]), "r"(a[3]), "r"(b[0]), "r"(b[1]));
}

// ---------------- smem layout ----------------
#define A_LDB  80                      // bytes per A row (64 data + 16 pad)
#define B_LDB  272                     // bytes per B row (256 data + 16 pad)
#define SZ_A   (128 * A_LDB)           // 10240
#define SZ_B   (32 * B_LDB)            // 8704
#define OFF_AH 0
#define OFF_AL SZ_A
#define OFF_BH (2 * SZ_A)
#define OFF_BL (2 * SZ_A + SZ_B)
#define BUF_SZ (2 * SZ_A + 2 * SZ_B)   // 37888
#define SMEM_TOTAL (2 * BUF_SZ)        // 75776

// ---------------- grouped GEMM via mma.sync bf16 (3-term split) ----------------
// L1: A = g_x* rows gathered via g_perm, K=256, N=512 -> writes g_h* (bias+relu, split)
// L2: A = g_h* (grouped), K=512, N=2048 -> writes out fp32 (scatter perm, bias)
template <bool L1>
__global__ __launch_bounds__(256, 1)
void gemm_mma(const float* __restrict__ bias,   // [NHEADS, N]
              float* __restrict__ Cout)         // L2 only
{
    const int K = L1 ? IN_F : HID;
    const int N = L1 ? HID  : OUT_F;
    const int hd     = blockIdx.z;
    const int mstart = g_off[hd];
    const int Mh     = g_off[hd + 1] - mstart;
    const int m0     = blockIdx.y * 128;
    if (m0 >= Mh) return;
    const int n0   = blockIdx.x * 128;
    const int mlim = Mh - m0;

    const __nv_bfloat16* Ah = L1 ? g_xh : g_hh;
    const __nv_bfloat16* Al = L1 ? g_xl : g_hl;
    const __nv_bfloat16* Bh = (L1 ? g_w1h : g_w2h) + (size_t)hd * K * N;
    const __nv_bfloat16* Bl = (L1 ? g_w1l : g_w2l) + (size_t)hd * K * N;

    extern __shared__ char smem[];
    const uint32_t sb = smem_u32(smem);
    const int tid  = threadIdx.x;
    const int wid  = tid >> 5;
    const int lane = tid & 31;
    const int mw = (wid & 3) * 32;       // warp m offset in tile
    const int nw = (wid >> 2) * 64;      // warp n offset in tile

    float acc[2][8][4];
#pragma unroll
    for (int a = 0; a < 2; a++)
#pragma unroll
        for (int b = 0; b < 8; b++)
#pragma unroll
            for (int c = 0; c < 4; c++) acc[a][b][c] = 0.f;

    const int nc = K / 32;
    uint4 pa[2][2], pb[2][2];
    const uint4 z4 = make_uint4(0, 0, 0, 0);

    // ---- prefetch chunk 0 ----
    {
        const int k0 = 0;
#pragma unroll
        for (int j = 0; j < 2; j++) {
            int idx = tid + j * 256;
            int row = idx >> 2, q = idx & 3;
            bool ok = row < mlim;
            if (ok) {
                int arow = L1 ? g_perm[mstart + m0 + row] : (mstart + m0 + row);
                size_t ao = ((size_t)arow * K + k0 + q * 8) >> 3;
                pa[0][j] = reinterpret_cast<const uint4*>(Ah)[ao];
                pa[1][j] = reinterpret_cast<const uint4*>(Al)[ao];
            } else { pa[0][j] = z4; pa[1][j] = z4; }
            int kb = idx >> 4, qb = idx & 15;
            size_t bo = ((size_t)(k0 + kb) * N + n0 + qb * 8) >> 3;
            pb[0][j] = reinterpret_cast<const uint4*>(Bh)[bo];
            pb[1][j] = reinterpret_cast<const uint4*>(Bl)[bo];
        }
    }

    for (int c = 0; c < nc; c++) {
        const uint32_t boff = (uint32_t)(c & 1) * BUF_SZ;
        // ---- store prefetched chunk into smem ----
#pragma unroll
        for (int j = 0; j < 2; j++) {
            int idx = tid + j * 256;
            int row = idx >> 2, q = idx & 3;
            uint32_t aoff = boff + row * A_LDB + q * 16;
            *reinterpret_cast<uint4*>(smem + aoff + OFF_AH) = pa[0][j];
            *reinterpret_cast<uint4*>(smem + aoff + OFF_AL) = pa[1][j];
            int kb = idx >> 4, qb = idx & 15;
            uint32_t boff2 = boff + kb * B_LDB + qb * 16;
            *reinterpret_cast<uint4*>(smem + boff2 + OFF_BH) = pb[0][j];
            *reinterpret_cast<uint4*>(smem + boff2 + OFF_BL) = pb[1][j];
        }
        __syncthreads();

        // ---- prefetch next chunk ----
        if (c + 1 < nc) {
            const int k0 = (c + 1) * 32;
#pragma unroll
            for (int j = 0; j < 2; j++) {
                int idx = tid + j * 256;
                int row = idx >> 2, q = idx & 3;
                bool ok = row < mlim;
                if (ok) {
                    int arow = L1 ? g_perm[mstart + m0 + row] : (mstart + m0 + row);
                    size_t ao = ((size_t)arow * K + k0 + q * 8) >> 3;
                    pa[0][j] = reinterpret_cast<const uint4*>(Ah)[ao];
                    pa[1][j] = reinterpret_cast<const uint4*>(Al)[ao];
                } else { pa[0][j] = z4; pa[1][j] = z4; }
                int kb = idx >> 4, qb = idx & 15;
                size_t bo = ((size_t)(k0 + kb) * N + n0 + qb * 8) >> 3;
                pb[0][j] = reinterpret_cast<const uint4*>(Bh)[bo];
                pb[1][j] = reinterpret_cast<const uint4*>(Bl)[bo];
            }
        }

        // ---- MMA on current buffer ----
        const int grp = lane >> 3, r = lane & 7;
#pragma unroll
        for (int ks = 0; ks < 2; ks++) {
            const int kk = ks * 16;
            uint32_t ah[2][4], al[2][4];
            {
                uint32_t arow_off = (uint32_t)((mw + (grp & 1) * 8 + r) * A_LDB
                                               + (kk + (grp >> 1) * 8) * 2);
                ldsm4(ah[0], sb + boff + OFF_AH + arow_off);
                ldsm4(ah[1], sb + boff + OFF_AH + arow_off + 16 * A_LDB);
                ldsm4(al[0], sb + boff + OFF_AL + arow_off);
                ldsm4(al[1], sb + boff + OFF_AL + arow_off + 16 * A_LDB);
            }
            uint32_t bh[16], bl[16];
            {
                uint32_t bbase = (uint32_t)((kk + (grp & 1) * 8 + r) * B_LDB
                                            + ((grp >> 1) * 8) * 2);
#pragma unroll
                for (int nb = 0; nb < 4; nb++) {
                    uint32_t na = bbase + (uint32_t)((nw + nb * 16) * 2);
                    ldsm4t(&bh[nb * 4], sb + boff + OFF_BH + na);
                    ldsm4t(&bl[nb * 4], sb + boff + OFF_BL + na);
                }
            }
#pragma unroll
            for (int mf = 0; mf < 2; mf++)
#pragma unroll
                for (int nf = 0; nf < 8; nf++) {
                    mma16816(acc[mf][nf], ah[mf], &bh[nf * 2]);
                    mma16816(acc[mf][nf], ah[mf], &bl[nf * 2]);
                    mma16816(acc[mf][nf], al[mf], &bh[nf * 2]);
                }
        }
        __syncthreads();
    }

    // ---- epilogue ----
    const int trow = lane >> 2;
    const int tcol = (lane & 3) * 2;
    const float* bs = bias + (size_t)hd * N + n0;
#pragma unroll
    for (int mf = 0; mf < 2; mf++) {
#pragma unroll
        for (int rr = 0; rr < 2; rr++) {
            int rloc = mw + mf * 16 + rr * 8 + trow;
            if (rloc >= mlim) continue;
            int grow = L1 ? (mstart + m0 + rloc) : g_perm[mstart + m0 + rloc];
#pragma unroll
            for (int nf = 0; nf < 8; nf++) {
                int col = nw + nf * 8 + tcol;
                float2 bv = *reinterpret_cast<const float2*>(&bs[col]);
                float v0 = acc[mf][nf][rr * 2 + 0] + bv.x;
                float v1 = acc[mf][nf][rr * 2 + 1] + bv.y;
                if (L1) {
                    v0 = fmaxf(v0, 0.f);
                    v1 = fmaxf(v1, 0.f);
                    float h0 = __bfloat162float(__float2bfloat16_rn(v0));
                    float h1 = __bfloat162float(__float2bfloat16_rn(v1));
                    size_t o = (size_t)grow * HID + n0 + col;
                    *reinterpret_cast<uint32_t*>(&g_hh[o]) = pack_bf2(h0, h1);
                    *reinterpret_cast<uint32_t*>(&g_hl[o]) = pack_bf2(v0 - h0, v1 - h1);
                } else {
                    float2 rv = make_float2(v0, v1);
                    *reinterpret_cast<float2*>(&Cout[(size_t)grow * OUT_F + n0 + col]) = rv;
                }
            }
        }
    }
}

// ---------------- launch ----------------
extern "C" void kernel_launch(void* const* d_in, const int* in_sizes, int n_in,
                              void* d_out, int out_size)
{
    const float* X   = (const float*)d_in[0];  // [4096, 256]
    const int*   idx = (const int*)  d_in[1];  // [4096]
    const float* W1  = (const float*)d_in[2];  // [8, 256, 512]
    const float* b1  = (const float*)d_in[3];  // [8, 512]
    const float* W2  = (const float*)d_in[4];  // [8, 512, 2048]
    const float* b2  = (const float*)d_in[5];  // [8, 2048]
    float*       out = (float*)d_out;          // [4096, 2048]

    static bool attr_done = false;
    if (!attr_done) {
        cudaFuncSetAttribute(gemm_mma<true>,  cudaFuncAttributeMaxDynamicSharedMemorySize, SMEM_TOTAL);
        cudaFuncSetAttribute(gemm_mma<false>, cudaFuncAttributeMaxDynamicSharedMemorySize, SMEM_TOTAL);
        attr_done = true;
    }

    // resolve device-symbol addresses for split targets
    __nv_bfloat16 *xh, *xl, *w1h, *w1l, *w2h, *w2l;
    cudaGetSymbolAddress((void**)&xh,  g_xh);
    cudaGetSymbolAddress((void**)&xl,  g_xl);
    cudaGetSymbolAddress((void**)&w1h, g_w1h);
    cudaGetSymbolAddress((void**)&w1l, g_w1l);
    cudaGetSymbolAddress((void**)&w2h, g_w2h);
    cudaGetSymbolAddress((void**)&w2l, g_w2l);

    k_group<<<1, 1024>>>(idx);

    const int nx  = BATCH * IN_F / 4;
    const int nw1 = NHEADS * IN_F * HID / 4;
    const int nw2 = NHEADS * HID * OUT_F / 4;
    k_split<<<(nx  + 255) / 256, 256>>>(X,  xh,  xl,  nx);
    k_split<<<(nw1 + 255) / 256, 256>>>(W1, w1h, w1l, nw1);
    k_split<<<(nw2 + 255) / 256, 256>>>(W2, w2h, w2l, nw2);

    const int row_tiles = BATCH / 128;   // worst case single head

    dim3 g1(HID / 128, row_tiles, NHEADS);
    gemm_mma<true><<<g1, 256, SMEM_TOTAL>>>(b1, nullptr);

    dim3 g2(OUT_F / 128, row_tiles, NHEADS);
    gemm_mma<false><<<g2, 256, SMEM_TOTAL>>>(b2, out);
}

// round 4
// speedup vs baseline: 2.0236x; 1.0686x over previous
#include <cuda_runtime.h>
#include <cuda_bf16.h>
#include <cstdint>

#define IN_F   256
#define HID    512
#define OUT_F  2048
#define NHEADS 8
#define BATCH  4096

// ---------------- device scratch ----------------
__device__ int g_off[NHEADS + 1];
__device__ int g_perm[BATCH];
__device__ __align__(16) __nv_bfloat16 g_hh[BATCH * HID];   // hidden hi, grouped rows
__device__ __align__(16) __nv_bfloat16 g_hl[BATCH * HID];   // hidden lo, grouped rows

// ---------------- grouping ----------------
__global__ void k_group(const int* __restrict__ idx) {
    __shared__ int cnt[NHEADS];
    __shared__ int cur[NHEADS];
    int t = threadIdx.x;                  // 1024 threads
    if (t < NHEADS) cnt[t] = 0;
    __syncthreads();
    int my[4];
#pragma unroll
    for (int i = 0; i < 4; i++) {
        my[i] = idx[t + i * 1024];
        atomicAdd(&cnt[my[i]], 1);
    }
    __syncthreads();
    if (t == 0) {
        int s = 0;
        for (int h = 0; h < NHEADS; h++) { g_off[h] = s; cur[h] = s; s += cnt[h]; }
        g_off[NHEADS] = s;
    }
    __syncthreads();
#pragma unroll
    for (int i = 0; i < 4; i++) {
        int p = atomicAdd(&cur[my[i]], 1);
        g_perm[p] = t + i * 1024;
    }
}

// ---------------- helpers ----------------
__device__ __forceinline__ uint32_t pack_bf2(float a, float b) {
    uint16_t ha = __bfloat16_as_ushort(__float2bfloat16_rn(a));
    uint16_t hb = __bfloat16_as_ushort(__float2bfloat16_rn(b));
    return (uint32_t)ha | ((uint32_t)hb << 16);
}
// split float4 -> (hi bf16x4, lo bf16x4) packed as uint2 each
__device__ __forceinline__ void split4(float4 v, uint2& uh, uint2& ul) {
    float h0 = __bfloat162float(__float2bfloat16_rn(v.x));
    float h1 = __bfloat162float(__float2bfloat16_rn(v.y));
    float h2 = __bfloat162float(__float2bfloat16_rn(v.z));
    float h3 = __bfloat162float(__float2bfloat16_rn(v.w));
    uh.x = pack_bf2(h0, h1);
    uh.y = pack_bf2(h2, h3);
    ul.x = pack_bf2(v.x - h0, v.y - h1);
    ul.y = pack_bf2(v.z - h2, v.w - h3);
}
__device__ __forceinline__ uint32_t smem_u32(const void* p) {
    uint32_t a;
    asm("{ .reg .u64 t; cvta.to.shared.u64 t, %1; cvt.u32.u64 %0, t; }" : "=r"(a) : "l"(p));
    return a;
}
__device__ __forceinline__ void ldsm4(uint32_t* r, uint32_t addr) {
    asm volatile("ldmatrix.sync.aligned.m8n8.x4.shared.b16 {%0,%1,%2,%3}, [%4];"
                 : "=r"(r[0]), "=r"(r[1]), "=r"(r[2]), "=r"(r[3]) : "r"(addr));
}
__device__ __forceinline__ void ldsm4t(uint32_t* r, uint32_t addr) {
    asm volatile("ldmatrix.sync.aligned.m8n8.x4.trans.shared.b16 {%0,%1,%2,%3}, [%4];"
                 : "=r"(r[0]), "=r"(r[1]), "=r"(r[2]), "=r"(r[3]) : "r"(addr));
}
__device__ __forceinline__ void mma16816(float* d, const uint32_t* a, const uint32_t* b) {
    asm volatile("mma.sync.aligned.m16n8k16.row.col.f32.bf16.bf16.f32 "
                 "{%0,%1,%2,%3}, {%4,%5,%6,%7}, {%8,%9}, {%0,%1,%2,%3};"
                 : "+f"(d[0]), "+f"(d[1]), "+f"(d[2]), "+f"(d[3])
                 : "r"(a[0]), "r"(a[1]), "r"(a[2]), "r"(a[3]), "r"(b[0]), "r"(b[1]));
}

// ---------------- smem layout (single buffer, < 48KB static) ----------------
#define A_LDB  80                      // bytes per A row (64 data + 16 pad)
#define B_LDB  272                     // bytes per B row (256 data + 16 pad)
#define SZ_A   (128 * A_LDB)           // 10240
#define SZ_B   (32 * B_LDB)            // 8704
#define OFF_AH 0
#define OFF_AL SZ_A
#define OFF_BH (2 * SZ_A)
#define OFF_BL (2 * SZ_A + SZ_B)
#define BUF_SZ (2 * SZ_A + 2 * SZ_B)   // 37888

// ---------------- grouped GEMM, fused fp32 -> bf16 hi/lo split ----------------
// L1: A = X fp32 rows gathered via g_perm (split in-kernel), B = W1 fp32,
//     epilogue: bias+relu, writes g_hh/g_hl (bf16 split, grouped rows)
// L2: A = g_hh/g_hl (grouped), B = W2 fp32, epilogue: bias, scatter to out fp32
template <bool L1>
__global__ __launch_bounds__(256, 2)
void gemm_mma(const float* __restrict__ Afp,
              const float* __restrict__ W,
              const float* __restrict__ bias,
              float* __restrict__ Cout)
{
    constexpr int K = L1 ? IN_F : HID;
    constexpr int N = L1 ? HID  : OUT_F;
    constexpr int NC = K / 32;

    const int hd     = blockIdx.z;
    const int mstart = g_off[hd];
    const int Mh     = g_off[hd + 1] - mstart;
    const int m0     = blockIdx.y * 128;
    if (m0 >= Mh) return;
    const int n0   = blockIdx.x * 128;
    const int mlim = Mh - m0;

    const float* Wh = W + (size_t)hd * K * N;

    __shared__ __align__(16) char smem[BUF_SZ];
    const uint32_t sb = smem_u32(smem);
    const int tid  = threadIdx.x;
    const int wid  = tid >> 5;
    const int lane = tid & 31;
    const int mw = (wid & 3) * 32;       // warp m offset
    const int nw = (wid >> 2) * 64;      // warp n offset

    float acc[2][8][4];
#pragma unroll
    for (int a = 0; a < 2; a++)
#pragma unroll
        for (int b = 0; b < 8; b++)
#pragma unroll
            for (int c = 0; c < 4; c++) acc[a][b][c] = 0.f;

    for (int c = 0; c < NC; c++) {
        const int k0 = c * 32;

        // ---- A tile: 128 x 32 ----
        if (L1) {
            // gather fp32 rows, split to bf16 hi/lo
#pragma unroll
            for (int j = 0; j < 4; j++) {
                int idx = tid + j * 256;     // 0..1023 float4 slots
                int row = idx >> 3, q = idx & 7;
                float4 v = make_float4(0.f, 0.f, 0.f, 0.f);
                if (row < mlim) {
                    int arow = g_perm[mstart + m0 + row];
                    v = *reinterpret_cast<const float4*>(&Afp[(size_t)arow * K + k0 + q * 4]);
                }
                uint2 uh, ul;
                split4(v, uh, ul);
                uint32_t ao = (uint32_t)(row * A_LDB + q * 8);
                *reinterpret_cast<uint2*>(smem + OFF_AH + ao) = uh;
                *reinterpret_cast<uint2*>(smem + OFF_AL + ao) = ul;
            }
        } else {
            // copy pre-split bf16 hi/lo rows
            const uint4 z4 = make_uint4(0, 0, 0, 0);
#pragma unroll
            for (int j = 0; j < 2; j++) {
                int idx = tid + j * 256;     // 0..511 uint4 slots (8 bf16 each)
                int row = idx >> 2, q = idx & 3;
                uint4 vh = z4, vl = z4;
                if (row < mlim) {
                    size_t eo = ((size_t)(mstart + m0 + row) * HID + k0 + q * 8) >> 3;
                    vh = reinterpret_cast<const uint4*>(g_hh)[eo];
                    vl = reinterpret_cast<const uint4*>(g_hl)[eo];
                }
                uint32_t ao = (uint32_t)(row * A_LDB + q * 16);
                *reinterpret_cast<uint4*>(smem + OFF_AH + ao) = vh;
                *reinterpret_cast<uint4*>(smem + OFF_AL + ao) = vl;
            }
        }

        // ---- B tile: 32 x 128 fp32 -> split ----
#pragma unroll
        for (int j = 0; j < 4; j++) {
            int idx = tid + j * 256;         // 0..1023 float4 slots
            int kb = idx >> 5, nq = idx & 31;
            float4 v = *reinterpret_cast<const float4*>(&Wh[(size_t)(k0 + kb) * N + n0 + nq * 4]);
            uint2 uh, ul;
            split4(v, uh, ul);
            uint32_t bo = (uint32_t)(kb * B_LDB + nq * 8);
            *reinterpret_cast<uint2*>(smem + OFF_BH + bo) = uh;
            *reinterpret_cast<uint2*>(smem + OFF_BL + bo) = ul;
        }
        __syncthreads();

        // ---- MMA: 3-term (Ah*Bh + Ah*Bl + Al*Bh) ----
        const int grp = lane >> 3, r = lane & 7;
#pragma unroll
        for (int ks = 0; ks < 2; ks++) {
            const int kk = ks * 16;
            uint32_t ah[2][4], al[2][4];
            {
                uint32_t arow_off = (uint32_t)((mw + (grp & 1) * 8 + r) * A_LDB
                                               + (kk + (grp >> 1) * 8) * 2);
                ldsm4(ah[0], sb + OFF_AH + arow_off);
                ldsm4(ah[1], sb + OFF_AH + arow_off + 16 * A_LDB);
                ldsm4(al[0], sb + OFF_AL + arow_off);
                ldsm4(al[1], sb + OFF_AL + arow_off + 16 * A_LDB);
            }
            uint32_t bbase = (uint32_t)((kk + (grp & 1) * 8 + r) * B_LDB
                                        + ((grp >> 1) * 8) * 2);
#pragma unroll
            for (int nb = 0; nb < 4; nb++) {
                uint32_t bh[4], bl[4];
                uint32_t na = bbase + (uint32_t)((nw + nb * 16) * 2);
                ldsm4t(bh, sb + OFF_BH + na);
                ldsm4t(bl, sb + OFF_BL + na);
#pragma unroll
                for (int mf = 0; mf < 2; mf++)
#pragma unroll
                    for (int nf = 0; nf < 2; nf++) {
                        float* d = acc[mf][nb * 2 + nf];
                        mma16816(d, ah[mf], &bh[nf * 2]);
                        mma16816(d, ah[mf], &bl[nf * 2]);
                        mma16816(d, al[mf], &bh[nf * 2]);
                    }
            }
        }
        __syncthreads();
    }

    // ---- epilogue ----
    const int trow = lane >> 2;
    const int tcol = (lane & 3) * 2;
    const float* bs = bias + (size_t)hd * N + n0;
#pragma unroll
    for (int mf = 0; mf < 2; mf++) {
#pragma unroll
        for (int rr = 0; rr < 2; rr++) {
            int rloc = mw + mf * 16 + rr * 8 + trow;
            if (rloc >= mlim) continue;
            int grow = L1 ? (mstart + m0 + rloc) : g_perm[mstart + m0 + rloc];
#pragma unroll
            for (int nf = 0; nf < 8; nf++) {
                int col = nw + nf * 8 + tcol;
                float2 bv = *reinterpret_cast<const float2*>(&bs[col]);
                float v0 = acc[mf][nf][rr * 2 + 0] + bv.x;
                float v1 = acc[mf][nf][rr * 2 + 1] + bv.y;
                if (L1) {
                    v0 = fmaxf(v0, 0.f);
                    v1 = fmaxf(v1, 0.f);
                    float h0 = __bfloat162float(__float2bfloat16_rn(v0));
                    float h1 = __bfloat162float(__float2bfloat16_rn(v1));
                    size_t o = (size_t)grow * HID + n0 + col;
                    *reinterpret_cast<uint32_t*>(&g_hh[o]) = pack_bf2(h0, h1);
                    *reinterpret_cast<uint32_t*>(&g_hl[o]) = pack_bf2(v0 - h0, v1 - h1);
                } else {
                    float2 rv = make_float2(v0, v1);
                    *reinterpret_cast<float2*>(&Cout[(size_t)grow * OUT_F + n0 + col]) = rv;
                }
            }
        }
    }
}

// ---------------- launch ----------------
extern "C" void kernel_launch(void* const* d_in, const int* in_sizes, int n_in,
                              void* d_out, int out_size)
{
    const float* X   = (const float*)d_in[0];  // [4096, 256]
    const int*   idx = (const int*)  d_in[1];  // [4096]
    const float* W1  = (const float*)d_in[2];  // [8, 256, 512]
    const float* b1  = (const float*)d_in[3];  // [8, 512]
    const float* W2  = (const float*)d_in[4];  // [8, 512, 2048]
    const float* b2  = (const float*)d_in[5];  // [8, 2048]
    float*       out = (float*)d_out;          // [4096, 2048]

    k_group<<<1, 1024>>>(idx);

    const int row_tiles = BATCH / 128;   // worst case: all rows in one head

    dim3 g1(HID / 128, row_tiles, NHEADS);
    gemm_mma<true><<<g1, 256>>>(X, W1, b1, nullptr);

    dim3 g2(OUT_F / 128, row_tiles, NHEADS);
    gemm_mma<false><<<g2, 256>>>(nullptr, W2, b2, out);
}

// round 5
// speedup vs baseline: 2.0241x; 1.0002x over previous
#include <cuda_runtime.h>
#include <cuda_bf16.h>
#include <cstdint>

#define IN_F   256
#define HID    512
#define OUT_F  2048
#define NHEADS 8
#define BATCH  4096

// ---------------- device scratch ----------------
__device__ int g_off[NHEADS + 1];
__device__ int g_perm[BATCH];
__device__ __align__(16) __nv_bfloat16 g_xh[BATCH * IN_F];
__device__ __align__(16) __nv_bfloat16 g_xl[BATCH * IN_F];
__device__ __align__(16) __nv_bfloat16 g_hh[BATCH * HID];
__device__ __align__(16) __nv_bfloat16 g_hl[BATCH * HID];
__device__ __align__(16) __nv_bfloat16 g_w1h[NHEADS * IN_F * HID];
__device__ __align__(16) __nv_bfloat16 g_w1l[NHEADS * IN_F * HID];
__device__ __align__(16) __nv_bfloat16 g_w2h[NHEADS * HID * OUT_F];
__device__ __align__(16) __nv_bfloat16 g_w2l[NHEADS * HID * OUT_F];

// ---------------- grouping (warp-aggregated atomics) ----------------
__global__ void k_group(const int* __restrict__ idx) {
    __shared__ int cnt[NHEADS];
    __shared__ int cur[NHEADS];
    int t = threadIdx.x;                  // 1024 threads
    int lane = t & 31;
    if (t < NHEADS) cnt[t] = 0;
    __syncthreads();
    int my[4];
#pragma unroll
    for (int i = 0; i < 4; i++) {
        my[i] = idx[t + i * 1024];
        unsigned m = __match_any_sync(0xffffffffu, my[i]);
        int leader = __ffs(m) - 1;
        if (lane == leader) atomicAdd(&cnt[my[i]], __popc(m));
    }
    __syncthreads();
    if (t == 0) {
        int s = 0;
        for (int h = 0; h < NHEADS; h++) { g_off[h] = s; cur[h] = s; s += cnt[h]; }
        g_off[NHEADS] = s;
    }
    __syncthreads();
#pragma unroll
    for (int i = 0; i < 4; i++) {
        unsigned m = __match_any_sync(0xffffffffu, my[i]);
        int leader = __ffs(m) - 1;
        int base = 0;
        if (lane == leader) base = atomicAdd(&cur[my[i]], __popc(m));
        base = __shfl_sync(0xffffffffu, base, leader);
        int rank = __popc(m & ((1u << lane) - 1));
        g_perm[base + rank] = t + i * 1024;
    }
}

// ---------------- helpers ----------------
__device__ __forceinline__ uint32_t pack_bf2(float a, float b) {
    uint16_t ha = __bfloat16_as_ushort(__float2bfloat16_rn(a));
    uint16_t hb = __bfloat16_as_ushort(__float2bfloat16_rn(b));
    return (uint32_t)ha | ((uint32_t)hb << 16);
}
__device__ __forceinline__ void split4(float4 v, uint2& uh, uint2& ul) {
    float h0 = __bfloat162float(__float2bfloat16_rn(v.x));
    float h1 = __bfloat162float(__float2bfloat16_rn(v.y));
    float h2 = __bfloat162float(__float2bfloat16_rn(v.z));
    float h3 = __bfloat162float(__float2bfloat16_rn(v.w));
    uh.x = pack_bf2(h0, h1);
    uh.y = pack_bf2(h2, h3);
    ul.x = pack_bf2(v.x - h0, v.y - h1);
    ul.y = pack_bf2(v.z - h2, v.w - h3);
}

#define NX4   (BATCH * IN_F / 4)
#define NW14  (NHEADS * IN_F * HID / 4)
#define NW24  (NHEADS * HID * OUT_F / 4)

// one kernel splits X, W1, W2
__global__ void k_split_all(const float* __restrict__ X,
                            const float* __restrict__ W1,
                            const float* __restrict__ W2) {
    int i = blockIdx.x * blockDim.x + threadIdx.x;
    const float* src;
    __nv_bfloat16 *hi, *lo;
    int j;
    if (i < NX4)              { src = X;  hi = g_xh;  lo = g_xl;  j = i; }
    else if (i < NX4 + NW14)  { src = W1; hi = g_w1h; lo = g_w1l; j = i - NX4; }
    else if (i < NX4 + NW14 + NW24) { src = W2; hi = g_w2h; lo = g_w2l; j = i - NX4 - NW14; }
    else return;
    float4 v = reinterpret_cast<const float4*>(src)[j];
    uint2 uh, ul;
    split4(v, uh, ul);
    reinterpret_cast<uint2*>(hi)[j] = uh;
    reinterpret_cast<uint2*>(lo)[j] = ul;
}

// ---------------- PTX helpers ----------------
__device__ __forceinline__ uint32_t smem_u32(const void* p) {
    uint32_t a;
    asm("{ .reg .u64 t; cvta.to.shared.u64 t, %1; cvt.u32.u64 %0, t; }" : "=r"(a) : "l"(p));
    return a;
}
__device__ __forceinline__ void cp_async16(uint32_t dst, const void* src, bool valid) {
    int sz = valid ? 16 : 0;
    asm volatile("cp.async.ca.shared.global [%0], [%1], 16, %2;"
                 :: "r"(dst), "l"(src), "r"(sz) : "memory");
}
#define CP_COMMIT() asm volatile("cp.async.commit_group;" ::: "memory")
__device__ __forceinline__ void ldsm4(uint32_t* r, uint32_t addr) {
    asm volatile("ldmatrix.sync.aligned.m8n8.x4.shared.b16 {%0,%1,%2,%3}, [%4];"
                 : "=r"(r[0]), "=r"(r[1]), "=r"(r[2]), "=r"(r[3]) : "r"(addr));
}
__device__ __forceinline__ void ldsm4t(uint32_t* r, uint32_t addr) {
    asm volatile("ldmatrix.sync.aligned.m8n8.x4.trans.shared.b16 {%0,%1,%2,%3}, [%4];"
                 : "=r"(r[0]), "=r"(r[1]), "=r"(r[2]), "=r"(r[3]) : "r"(addr));
}
__device__ __forceinline__ void mma16816(float* d, const uint32_t* a, const uint32_t* b) {
    asm volatile("mma.sync.aligned.m16n8k16.row.col.f32.bf16.bf16.f32 "
                 "{%0,%1,%2,%3}, {%4,%5,%6,%7}, {%8,%9}, {%0,%1,%2,%3};"
                 : "+f"(d[0]), "+f"(d[1]), "+f"(d[2]), "+f"(d[3])
                 : "r"(a[0]), "r"(a[1]), "r"(a[2]), "r"(a[3]), "r"(b[0]), "r"(b[1]));
}

// ---------------- smem layout (double buffer, dynamic) ----------------
#define A_LDB  80
#define B_LDB  272
#define SZ_A   (128 * A_LDB)           // 10240
#define SZ_B   (32 * B_LDB)            // 8704
#define OFF_AH 0
#define OFF_AL SZ_A
#define OFF_BH (2 * SZ_A)
#define OFF_BL (2 * SZ_A + SZ_B)
#define BUF_SZ (2 * SZ_A + 2 * SZ_B)   // 37888
#define SMEM_TOTAL (2 * BUF_SZ)        // 75776

// ---------------- grouped GEMM: pre-split bf16 hi/lo, cp.async pipeline ----------------
template <bool L1>
__global__ __launch_bounds__(256, 2)
void gemm_mma(const float* __restrict__ bias, float* __restrict__ Cout)
{
    constexpr int K = L1 ? IN_F : HID;
    constexpr int N = L1 ? HID  : OUT_F;
    constexpr int NC = K / 32;

    const int hd     = blockIdx.z;
    const int mstart = g_off[hd];
    const int Mh     = g_off[hd + 1] - mstart;
    const int m0     = blockIdx.y * 128;
    if (m0 >= Mh) return;
    const int n0   = blockIdx.x * 128;
    const int mlim = Mh - m0;

    const __nv_bfloat16* Ah = L1 ? g_xh : g_hh;
    const __nv_bfloat16* Al = L1 ? g_xl : g_hl;
    const __nv_bfloat16* Bh = (L1 ? g_w1h : g_w2h) + (size_t)hd * K * N;
    const __nv_bfloat16* Bl = (L1 ? g_w1l : g_w2l) + (size_t)hd * K * N;

    extern __shared__ __align__(16) char smem[];
    const uint32_t sb = smem_u32(smem);
    const int tid  = threadIdx.x;
    const int wid  = tid >> 5;
    const int lane = tid & 31;
    const int mw = (wid & 3) * 32;
    const int nw = (wid >> 2) * 64;

    // per-thread load slots (computed once)
    // A: 2 slots: row = idx>>2 (0..127), q = idx&3 (uint4 within 32 bf16)
    int a_row[2], a_q[2], a_src[2];
    bool a_ok[2];
    // B: 2 slots: kb = idx>>4 (0..31), qb = idx&15
    int b_kb[2], b_qb[2];
#pragma unroll
    for (int j = 0; j < 2; j++) {
        int idx = tid + j * 256;
        a_row[j] = idx >> 2; a_q[j] = idx & 3;
        a_ok[j]  = a_row[j] < mlim;
        a_src[j] = a_ok[j] ? (L1 ? g_perm[mstart + m0 + a_row[j]]
                                 : (mstart + m0 + a_row[j])) : 0;
        b_kb[j] = idx >> 4; b_qb[j] = idx & 15;
    }

    auto prefetch = [&](int c) {
        const int k0 = c * 32;
        const uint32_t bo = (uint32_t)(c & 1) * BUF_SZ;
#pragma unroll
        for (int j = 0; j < 2; j++) {
            uint32_t ad = sb + bo + (uint32_t)(a_row[j] * A_LDB + a_q[j] * 16);
            size_t asrc = (size_t)a_src[j] * K + k0 + a_q[j] * 8;
            cp_async16(ad + OFF_AH, Ah + asrc, a_ok[j]);
            cp_async16(ad + OFF_AL, Al + asrc, a_ok[j]);
            uint32_t bd = sb + bo + (uint32_t)(b_kb[j] * B_LDB + b_qb[j] * 16);
            size_t bsrc = (size_t)(k0 + b_kb[j]) * N + n0 + b_qb[j] * 8;
            cp_async16(bd + OFF_BH, Bh + bsrc, true);
            cp_async16(bd + OFF_BL, Bl + bsrc, true);
        }
    };

    float acc[2][8][4];
#pragma unroll
    for (int a = 0; a < 2; a++)
#pragma unroll
        for (int b = 0; b < 8; b++)
#pragma unroll
            for (int c = 0; c < 4; c++) acc[a][b][c] = 0.f;

    prefetch(0);
    CP_COMMIT();

    for (int c = 0; c < NC; c++) {
        __syncthreads();   // all warps done reading the buffer we're about to overwrite
        if (c + 1 < NC) {
            prefetch(c + 1);
            CP_COMMIT();
            asm volatile("cp.async.wait_group 1;" ::: "memory");
        } else {
            asm volatile("cp.async.wait_group 0;" ::: "memory");
        }
        __syncthreads();   // chunk c visible to all warps

        const uint32_t bo = (uint32_t)(c & 1) * BUF_SZ;
        const int grp = lane >> 3, r = lane & 7;
#pragma unroll
        for (int ks = 0; ks < 2; ks++) {
            const int kk = ks * 16;
            uint32_t ah[2][4], al[2][4];
            {
                uint32_t arow_off = (uint32_t)((mw + (grp & 1) * 8 + r) * A_LDB
                                               + (kk + (grp >> 1) * 8) * 2);
                ldsm4(ah[0], sb + bo + OFF_AH + arow_off);
                ldsm4(ah[1], sb + bo + OFF_AH + arow_off + 16 * A_LDB);
                ldsm4(al[0], sb + bo + OFF_AL + arow_off);
                ldsm4(al[1], sb + bo + OFF_AL + arow_off + 16 * A_LDB);
            }
            uint32_t bbase = (uint32_t)((kk + (grp & 1) * 8 + r) * B_LDB
                                        + ((grp >> 1) * 8) * 2);
#pragma unroll
            for (int nb = 0; nb < 4; nb++) {
                uint32_t bh[4], bl[4];
                uint32_t na = bbase + (uint32_t)((nw + nb * 16) * 2);
                ldsm4t(bh, sb + bo + OFF_BH + na);
                ldsm4t(bl, sb + bo + OFF_BL + na);
#pragma unroll
                for (int mf = 0; mf < 2; mf++)
#pragma unroll
                    for (int nf = 0; nf < 2; nf++) {
                        float* d = acc[mf][nb * 2 + nf];
                        mma16816(d, ah[mf], &bh[nf * 2]);
                        mma16816(d, ah[mf], &bl[nf * 2]);
                        mma16816(d, al[mf], &bh[nf * 2]);
                    }
            }
        }
    }

    // ---- epilogue ----
    const int trow = lane >> 2;
    const int tcol = (lane & 3) * 2;
    const float* bs = bias + (size_t)hd * N + n0;
#pragma unroll
    for (int mf = 0; mf < 2; mf++) {
#pragma unroll
        for (int rr = 0; rr < 2; rr++) {
            int rloc = mw + mf * 16 + rr * 8 + trow;
            if (rloc >= mlim) continue;
            int grow = L1 ? (mstart + m0 + rloc) : g_perm[mstart + m0 + rloc];
#pragma unroll
            for (int nf = 0; nf < 8; nf++) {
                int col = nw + nf * 8 + tcol;
                float2 bv = *reinterpret_cast<const float2*>(&bs[col]);
                float v0 = acc[mf][nf][rr * 2 + 0] + bv.x;
                float v1 = acc[mf][nf][rr * 2 + 1] + bv.y;
                if (L1) {
                    v0 = fmaxf(v0, 0.f);
                    v1 = fmaxf(v1, 0.f);
                    float h0 = __bfloat162float(__float2bfloat16_rn(v0));
                    float h1 = __bfloat162float(__float2bfloat16_rn(v1));
                    size_t o = (size_t)grow * HID + n0 + col;
                    *reinterpret_cast<uint32_t*>(&g_hh[o]) = pack_bf2(h0, h1);
                    *reinterpret_cast<uint32_t*>(&g_hl[o]) = pack_bf2(v0 - h0, v1 - h1);
                } else {
                    float2 rv = make_float2(v0, v1);
                    *reinterpret_cast<float2*>(&Cout[(size_t)grow * OUT_F + n0 + col]) = rv;
                }
            }
        }
    }
}

// ---------------- launch ----------------
extern "C" void kernel_launch(void* const* d_in, const int* in_sizes, int n_in,
                              void* d_out, int out_size)
{
    const float* X   = (const float*)d_in[0];
    const int*   idx = (const int*)  d_in[1];
    const float* W1  = (const float*)d_in[2];
    const float* b1  = (const float*)d_in[3];
    const float* W2  = (const float*)d_in[4];
    const float* b2  = (const float*)d_in[5];
    float*       out = (float*)d_out;

    static bool attr_done = false;
    if (!attr_done) {
        cudaFuncSetAttribute(gemm_mma<true>,  cudaFuncAttributeMaxDynamicSharedMemorySize, SMEM_TOTAL);
        cudaFuncSetAttribute(gemm_mma<false>, cudaFuncAttributeMaxDynamicSharedMemorySize, SMEM_TOTAL);
        attr_done = true;
    }

    k_group<<<1, 1024>>>(idx);

    const int ntot = NX4 + NW14 + NW24;
    k_split_all<<<(ntot + 255) / 256, 256>>>(X, W1, W2);

    const int row_tiles = BATCH / 128;

    dim3 g1(HID / 128, row_tiles, NHEADS);
    gemm_mma<true><<<g1, 256, SMEM_TOTAL>>>(b1, nullptr);

    dim3 g2(OUT_F / 128, row_tiles, NHEADS);
    gemm_mma<false><<<g2, 256, SMEM_TOTAL>>>(b2, out);
}